// round 3
// baseline (speedup 1.0000x reference)
#include <cuda_runtime.h>
#include <cuda_bf16.h>
#include <math.h>

#define SEQ      1024
#define DMODEL   4096
#define NHEADS   32
#define NKV      8
#define HDIM     128
#define FETCHMAX 204
#define ALPHA_M  5.0f
#define SCALING  0.08838834764831845f

// ---------------- device scratch (no allocations allowed) ----------------
__device__ float g_q[SEQ * DMODEL];           // 16 MB
__device__ float g_k[SEQ * NKV * HDIM];       // 4 MB
__device__ float g_v[SEQ * NKV * HDIM];       // 4 MB
__device__ float g_scores[33554432];          // 32*1024*1024 = 128 MB (scores -> probs in place)
__device__ float g_attn[SEQ * DMODEL];        // 16 MB
__device__ float g_max0[SEQ];
__device__ int   g_fetch[SEQ];

// ---------------- block reductions (blockDim.x == 256) ----------------
__device__ __forceinline__ int blockSumI(int v) {
    __shared__ int sm[8];
    int lane = threadIdx.x & 31, wid = threadIdx.x >> 5;
    #pragma unroll
    for (int o = 16; o; o >>= 1) v += __shfl_xor_sync(0xffffffffu, v, o);
    if (lane == 0) sm[wid] = v;
    __syncthreads();
    if (wid == 0) {
        int x = (lane < 8) ? sm[lane] : 0;
        #pragma unroll
        for (int o = 16; o; o >>= 1) x += __shfl_xor_sync(0xffffffffu, x, o);
        if (lane == 0) sm[0] = x;
    }
    __syncthreads();
    v = sm[0];
    __syncthreads();
    return v;
}

__device__ __forceinline__ float blockSumF(float v) {
    __shared__ float sm[8];
    int lane = threadIdx.x & 31, wid = threadIdx.x >> 5;
    #pragma unroll
    for (int o = 16; o; o >>= 1) v += __shfl_xor_sync(0xffffffffu, v, o);
    if (lane == 0) sm[wid] = v;
    __syncthreads();
    if (wid == 0) {
        float x = (lane < 8) ? sm[lane] : 0.0f;
        #pragma unroll
        for (int o = 16; o; o >>= 1) x += __shfl_xor_sync(0xffffffffu, x, o);
        if (lane == 0) sm[0] = x;
    }
    __syncthreads();
    v = sm[0];
    __syncthreads();
    return v;
}

__device__ __forceinline__ float blockMaxF(float v) {
    __shared__ float sm[8];
    int lane = threadIdx.x & 31, wid = threadIdx.x >> 5;
    #pragma unroll
    for (int o = 16; o; o >>= 1) v = fmaxf(v, __shfl_xor_sync(0xffffffffu, v, o));
    if (lane == 0) sm[wid] = v;
    __syncthreads();
    if (wid == 0) {
        float x = (lane < 8) ? sm[lane] : -3.0e38f;
        #pragma unroll
        for (int o = 16; o; o >>= 1) x = fmaxf(x, __shfl_xor_sync(0xffffffffu, x, o));
        if (lane == 0) sm[0] = x;
    }
    __syncthreads();
    v = sm[0];
    __syncthreads();
    return v;
}

// ---------------- generic 128x128 tiled SGEMM ----------------
// BT=true : C[m,n] = alpha * sum_k A[m,k] * B[n,k]   (B is [N][K] row-major)
// BT=false: C[m,n] = alpha * sum_k A[m,k] * B[k,n]   (B is [K][N] row-major)
// Batched over blockIdx.z: A += z*sA, B += (z/zdivB)*sB, C += z*sC.
// All M,N multiples of 128; K multiple of 8. No bounds checks.
template <bool BT>
__global__ __launch_bounds__(256)
void sgemm(const float* __restrict__ A, const float* __restrict__ B, float* __restrict__ C,
           int K, int lda, int ldb, int ldc,
           long sA, long sB, long sC, int zdivB, float alpha)
{
    int z = blockIdx.z;
    A += (long)z * sA;
    B += (long)(z / zdivB) * sB;
    C += (long)z * sC;

    const int m0 = blockIdx.y * 128;
    const int n0 = blockIdx.x * 128;

    __shared__ float As[8][128];
    __shared__ float Bs[8][128];

    const int tid  = threadIdx.x;
    const int lrow = tid >> 1;          // 0..127
    const int lseg = (tid & 1) * 4;     // 0 or 4
    const int brow = tid >> 5;          // 0..7  (NN mode k index)
    const int bcol = (tid & 31) * 4;    // 0..124

    const int ty = tid >> 4, tx = tid & 15;
    const int r0 = ty * 8, c0 = tx * 8;

    float acc[8][8];
    #pragma unroll
    for (int i = 0; i < 8; ++i)
        #pragma unroll
        for (int j = 0; j < 8; ++j) acc[i][j] = 0.0f;

    for (int k0 = 0; k0 < K; k0 += 8) {
        float4 av = *(const float4*)(A + (long)(m0 + lrow) * lda + k0 + lseg);
        float4 bv;
        if (BT) bv = *(const float4*)(B + (long)(n0 + lrow) * ldb + k0 + lseg);
        else    bv = *(const float4*)(B + (long)(k0 + brow) * ldb + n0 + bcol);

        __syncthreads();   // previous tile fully consumed
        As[lseg + 0][lrow] = av.x; As[lseg + 1][lrow] = av.y;
        As[lseg + 2][lrow] = av.z; As[lseg + 3][lrow] = av.w;
        if (BT) {
            Bs[lseg + 0][lrow] = bv.x; Bs[lseg + 1][lrow] = bv.y;
            Bs[lseg + 2][lrow] = bv.z; Bs[lseg + 3][lrow] = bv.w;
        } else {
            *(float4*)&Bs[brow][bcol] = bv;
        }
        __syncthreads();

        #pragma unroll
        for (int kk = 0; kk < 8; ++kk) {
            float a[8], b[8];
            *(float4*)&a[0] = *(const float4*)&As[kk][r0];
            *(float4*)&a[4] = *(const float4*)&As[kk][r0 + 4];
            *(float4*)&b[0] = *(const float4*)&Bs[kk][c0];
            *(float4*)&b[4] = *(const float4*)&Bs[kk][c0 + 4];
            #pragma unroll
            for (int i = 0; i < 8; ++i)
                #pragma unroll
                for (int j = 0; j < 8; ++j)
                    acc[i][j] = fmaf(a[i], b[j], acc[i][j]);
        }
    }

    #pragma unroll
    for (int i = 0; i < 8; ++i) {
        float4 o0 = make_float4(acc[i][0] * alpha, acc[i][1] * alpha, acc[i][2] * alpha, acc[i][3] * alpha);
        float4 o1 = make_float4(acc[i][4] * alpha, acc[i][5] * alpha, acc[i][6] * alpha, acc[i][7] * alpha);
        float* cp = C + (long)(m0 + r0 + i) * ldc + n0 + c0;
        *(float4*)cp       = o0;
        *(float4*)(cp + 4) = o1;
    }
}

// ---------------- RoPE (in place), one thread per (t, head, d<64) pair ----------------
__global__ void rope_kernel(float* __restrict__ x, const float* __restrict__ cs,
                            const float* __restrict__ sn, int nheads)
{
    int idx = blockIdx.x * blockDim.x + threadIdx.x;
    int total = SEQ * nheads * 64;
    if (idx >= total) return;
    int d = idx & 63;
    int rest = idx >> 6;
    int h = rest % nheads;
    int t = rest / nheads;
    float* p = x + ((long)t * nheads + h) * HDIM;
    float x1 = p[d], x2 = p[d + 64];
    float c1 = cs[t * HDIM + d],      s1 = sn[t * HDIM + d];
    float c2 = cs[t * HDIM + d + 64], s2 = sn[t * HDIM + d + 64];
    p[d]      = x1 * c1 - x2 * s1;   // rotate_half: first half gets -x2
    p[d + 64] = x2 * c2 + x1 * s2;   // second half gets +x1
}

// ---------------- stats: head-0 causal row max ----------------
__global__ __launch_bounds__(256)
void row_max0(const float* __restrict__ scores, float* __restrict__ max0)
{
    int t = blockIdx.x;
    int L = t + 1;
    const float* row = scores + ((size_t)t << 10);
    float m = -3.0e38f;
    for (int j = threadIdx.x; j < L; j += 256) m = fmaxf(m, row[j]);
    m = blockMaxF(m);
    if (threadIdx.x == 0) max0[t] = m;
}

// ---------------- stats: fetch_num[t] = min(204, (sum_h count_h) >> 5) ----------------
__global__ __launch_bounds__(256)
void fetch_kernel(const float* __restrict__ scores, const float* __restrict__ max0,
                  int* __restrict__ fetch)
{
    int t = blockIdx.x;
    int L = t + 1;
    float thr = max0[t] - ALPHA_M;
    int c = 0;
    for (int h = 0; h < NHEADS; ++h) {
        const float* row = scores + ((size_t)h << 20) + ((size_t)t << 10);
        for (int j = threadIdx.x; j < L; j += 256) c += (row[j] >= thr);
    }
    c = blockSumI(c);
    if (threadIdx.x == 0) fetch[t] = min(FETCHMAX, c >> 5);
}

// ---------------- masked softmax with exact top-k (radix select) ----------------
__global__ __launch_bounds__(256)
void mask_softmax(float* __restrict__ scores, const int* __restrict__ fetch)
{
    int t = blockIdx.x, h = blockIdx.y;
    float* row = scores + ((size_t)h << 20) + ((size_t)t << 10);

    __shared__ float    sr[SEQ];
    __shared__ unsigned su[SEQ];

    int tid = threadIdx.x;

    bool select = (t >= FETCHMAX);
    int kk = 0;
    if (select) {
        kk = fetch[t];
        if (kk <= 0) select = false;  // degenerate: all-NEG mask -> softmax over full raw row
    }
    int L = (t < FETCHMAX) ? (t + 1) : (select ? (t + 1) : SEQ);

    // load row, build sortable keys, track max
    float lm = -3.0e38f;
    for (int j = tid; j < L; j += 256) {
        float s = row[j];
        sr[j] = s;
        unsigned u = __float_as_uint(s);
        u = (u & 0x80000000u) ? ~u : (u | 0x80000000u);
        su[j] = u;
        lm = fmaxf(lm, s);
    }
    __syncthreads();
    float m = blockMaxF(lm);   // == max over kept set (rank 0 always kept)

    unsigned vk = 0;
    int ties = 0;
    bool simple = true;
    if (select) {
        // MSB-first radix select: find k-th largest key
        int k = kk;
        unsigned prefix = 0;
        for (int bit = 31; bit >= 0; --bit) {
            unsigned tgt = (prefix >> bit) | 1u;
            int c = 0;
            for (int j = tid; j < L; j += 256) c += ((su[j] >> bit) == tgt);
            c = blockSumI(c);
            if (c >= k) prefix |= (1u << bit);
            else        k -= c;
        }
        vk = prefix;
        ties = k;                       // how many elements == vk are kept (by index order)
        int ce = 0;
        for (int j = tid; j < L; j += 256) ce += (su[j] == vk);
        ce = blockSumI(ce);
        simple = (ce == ties);          // common case: keep all equals
    }

    float ls = 0.0f;
    for (int j = tid; j < L; j += 256) {
        bool kept = true;
        if (select) {
            unsigned u = su[j];
            if (u > vk)      kept = true;
            else if (u < vk) kept = false;
            else if (simple) kept = true;
            else {           // rare exact-tie path: stable-by-index
                int r = 0;
                for (int j2 = 0; j2 < j; ++j2) r += (su[j2] == vk);
                kept = (r < ties);
            }
        }
        float e = kept ? expf(sr[j] - m) : 0.0f;
        sr[j] = e;
        ls += e;
    }
    float Z = blockSumF(ls);
    float inv = 1.0f / Z;
    for (int j = tid; j < SEQ; j += 256)
        row[j] = (j < L) ? sr[j] * inv : 0.0f;
}

// ---------------- launch ----------------
extern "C" void kernel_launch(void* const* d_in, const int* in_sizes, int n_in,
                              void* d_out, int out_size)
{
    const float* hs = (const float*)d_in[0];
    const float* cs = (const float*)d_in[1];
    const float* sn = (const float*)d_in[2];
    const float* Wq = (const float*)d_in[3];
    const float* Wk = (const float*)d_in[4];
    const float* Wv = (const float*)d_in[5];
    const float* Wo = (const float*)d_in[6];
    float* out = (float*)d_out;

    float *qp, *kp, *vp, *sp, *ap, *m0p;
    int* fp;
    cudaGetSymbolAddress((void**)&qp,  g_q);
    cudaGetSymbolAddress((void**)&kp,  g_k);
    cudaGetSymbolAddress((void**)&vp,  g_v);
    cudaGetSymbolAddress((void**)&sp,  g_scores);
    cudaGetSymbolAddress((void**)&ap,  g_attn);
    cudaGetSymbolAddress((void**)&m0p, g_max0);
    cudaGetSymbolAddress((void**)&fp,  g_fetch);

    // QKV projections: X [1024,4096] @ W^T
    sgemm<true><<<dim3(DMODEL / 128, SEQ / 128, 1), 256>>>(hs, Wq, qp, DMODEL, DMODEL, DMODEL, DMODEL, 0, 0, 0, 1, 1.0f);
    sgemm<true><<<dim3(8, 8, 1), 256>>>(hs, Wk, kp, DMODEL, DMODEL, DMODEL, NKV * HDIM, 0, 0, 0, 1, 1.0f);
    sgemm<true><<<dim3(8, 8, 1), 256>>>(hs, Wv, vp, DMODEL, DMODEL, DMODEL, NKV * HDIM, 0, 0, 0, 1, 1.0f);

    // RoPE in place
    rope_kernel<<<(SEQ * NHEADS * 64) / 256, 256>>>(qp, cs, sn, NHEADS);
    rope_kernel<<<(SEQ * NKV * 64) / 256, 256>>>(kp, cs, sn, NKV);

    // scores[h] = scaling * q_h @ k_{h/4}^T   (batched over 32 heads, GQA via zdivB=4)
    sgemm<true><<<dim3(8, 8, NHEADS), 256>>>(qp, kp, sp, HDIM, DMODEL, NKV * HDIM, SEQ,
                                             /*sA=*/HDIM, /*sB=*/HDIM, /*sC=*/(long)SEQ * SEQ, /*zdivB=*/4, SCALING);

    // dynamic mask stats + masked softmax (scores -> probs in place)
    row_max0<<<SEQ, 256>>>(sp, m0p);
    fetch_kernel<<<SEQ, 256>>>(sp, m0p, fp);
    mask_softmax<<<dim3(SEQ, NHEADS), 256>>>(sp, fp);

    // attn_out[h] = probs_h @ v_{h/4}   (NN GEMM, batched)
    sgemm<false><<<dim3(1, 8, NHEADS), 256>>>(sp, vp, ap, SEQ, SEQ, NKV * HDIM, DMODEL,
                                              /*sA=*/(long)SEQ * SEQ, /*sB=*/HDIM, /*sC=*/HDIM, /*zdivB=*/4, 1.0f);

    // output projection
    sgemm<true><<<dim3(32, 8, 1), 256>>>(ap, Wo, out, DMODEL, DMODEL, DMODEL, DMODEL, 0, 0, 0, 1, 1.0f);
}

// round 12
// speedup vs baseline: 1.9818x; 1.9818x over previous
#include <cuda_runtime.h>
#include <cuda_bf16.h>
#include <math.h>
#include <stdint.h>

#define SEQ      1024
#define DMODEL   4096
#define NHEADS   32
#define NKV      8
#define HDIM     128
#define FETCHMAX 204
#define ALPHA_M  5.0f
#define SCALING  0.08838834764831845f

// ---------------- device scratch (no allocations allowed) ----------------
__device__ float g_q[SEQ * DMODEL];
__device__ float g_k[SEQ * NKV * HDIM];
__device__ float g_v[SEQ * NKV * HDIM];
__device__ float g_scores[33554432];          // 128 MB fp32 scores
__device__ float g_attn[SEQ * DMODEL];
__device__ float g_max0[SEQ];
__device__ int   g_fetch[SEQ];

__device__ __nv_bfloat16 g_hsh[SEQ * DMODEL],  g_hsl[SEQ * DMODEL];
__device__ __nv_bfloat16 g_Wqh[DMODEL * DMODEL], g_Wql[DMODEL * DMODEL];
__device__ __nv_bfloat16 g_Wkh[NKV * HDIM * DMODEL], g_Wkl[NKV * HDIM * DMODEL];
__device__ __nv_bfloat16 g_Wvh[NKV * HDIM * DMODEL], g_Wvl[NKV * HDIM * DMODEL];
__device__ __nv_bfloat16 g_Woh[DMODEL * DMODEL], g_Wol[DMODEL * DMODEL];
__device__ __nv_bfloat16 g_qh[SEQ * DMODEL],   g_ql[SEQ * DMODEL];
__device__ __nv_bfloat16 g_kh[SEQ * NKV * HDIM], g_kl[SEQ * NKV * HDIM];
__device__ __nv_bfloat16 g_vTh[NKV * HDIM * SEQ], g_vTl[NKV * HDIM * SEQ];
__device__ __nv_bfloat16 g_ph[33554432], g_pl[33554432];
__device__ __nv_bfloat16 g_ah[SEQ * DMODEL],  g_al[SEQ * DMODEL];

// ---------------- PTX helpers (arch-agnostic: ldmatrix + mma.sync, sm_80+) ----------------
__device__ __forceinline__ uint32_t smem_u32(const void* p) {
    uint32_t a;
    asm("{ .reg .u64 t; cvta.to.shared.u64 t, %1; cvt.u32.u64 %0, t; }" : "=r"(a) : "l"(p));
    return a;
}
__device__ __forceinline__ void ldsm4(uint32_t* r, uint32_t a) {
    asm volatile("ldmatrix.sync.aligned.m8n8.x4.shared.b16 {%0,%1,%2,%3}, [%4];"
        : "=r"(r[0]), "=r"(r[1]), "=r"(r[2]), "=r"(r[3]) : "r"(a));
}
__device__ __forceinline__ void ldsm2(uint32_t* r, uint32_t a) {
    asm volatile("ldmatrix.sync.aligned.m8n8.x2.shared.b16 {%0,%1}, [%2];"
        : "=r"(r[0]), "=r"(r[1]) : "r"(a));
}
__device__ __forceinline__ void mma16816(float* c, const uint32_t* a, const uint32_t* b) {
    asm volatile("mma.sync.aligned.m16n8k16.row.col.f32.bf16.bf16.f32 "
        "{%0,%1,%2,%3}, {%4,%5,%6,%7}, {%8,%9}, {%0,%1,%2,%3};"
        : "+f"(c[0]), "+f"(c[1]), "+f"(c[2]), "+f"(c[3])
        : "r"(a[0]), "r"(a[1]), "r"(a[2]), "r"(a[3]), "r"(b[0]), "r"(b[1]));
}

// ---------------- bf16x3 BT GEMM via mma.sync: C[m,n] = alpha * sum_k A[m,k]*B[n,k] ----------------
// A,B are hi/lo bf16 pairs, both K-major row-major ([M][K], [N][K]).
// CTA tile 128x128, K-chunks of 32, double-buffered SMEM, 8 warps of 32x64.
#define KC       32
#define ASTRIDE  40                     // halves per SMEM row (32 + 8 pad -> conflict-free ldmatrix)
#define MATB     (128 * ASTRIDE * 2)    // 10240 B per matrix tile
#define BUFB     (4 * MATB)             // Ah, Al, Bh, Bl
#define GEMM_SMEM (2 * BUFB)            // 81920 B double-buffered

__global__ __launch_bounds__(256, 1)
void gemm_mma(const __nv_bfloat16* __restrict__ Ah, const __nv_bfloat16* __restrict__ Al,
              const __nv_bfloat16* __restrict__ Bh, const __nv_bfloat16* __restrict__ Bl,
              float* __restrict__ C, int K, int lda, int ldb, int ldc,
              long sA, long sB, long sC, int zdivB, float alpha)
{
    extern __shared__ char smem[];
    const uint32_t sb = smem_u32(smem);
    const int tid = threadIdx.x, wid = tid >> 5, lane = tid & 31;
    const int z = blockIdx.z;
    Ah += (long)z * sA; Al += (long)z * sA;
    Bh += (long)(z / zdivB) * sB; Bl += (long)(z / zdivB) * sB;
    C  += (long)z * sC;
    const int m0 = blockIdx.y * 128, n0 = blockIdx.x * 128;
    const int wm0 = (wid & 3) * 32, wn0 = (wid >> 2) * 64;

    float acc[2][8][4];
    #pragma unroll
    for (int mt = 0; mt < 2; ++mt)
        #pragma unroll
        for (int nt = 0; nt < 8; ++nt)
            #pragma unroll
            for (int i = 0; i < 4; ++i) acc[mt][nt][i] = 0.0f;

    const __nv_bfloat16* srcs[4] = { Ah, Al, Bh, Bl };
    const int lds[4]  = { lda, lda, ldb, ldb };
    const int rowb[4] = { m0, m0, n0, n0 };

    float4 rg[8];
    auto do_ldg = [&](int k0) {
        #pragma unroll
        for (int t = 0; t < 4; ++t)
            #pragma unroll
            for (int i = 0; i < 2; ++i) {
                int seg = i * 256 + tid;          // 512 segs of 16B = 128 rows x 4
                int row = seg >> 2, cs = seg & 3;
                rg[t * 2 + i] = *(const float4*)(srcs[t] + (long)(rowb[t] + row) * lds[t] + k0 + cs * 8);
            }
    };
    auto do_sts = [&](int buf) {
        #pragma unroll
        for (int t = 0; t < 4; ++t) {
            char* tb = smem + buf * BUFB + t * MATB;
            #pragma unroll
            for (int i = 0; i < 2; ++i) {
                int seg = i * 256 + tid;
                int row = seg >> 2, cs = seg & 3;
                *(float4*)(tb + row * (ASTRIDE * 2) + cs * 16) = rg[t * 2 + i];
            }
        }
    };
    auto compute = [&](int buf) {
        const uint32_t base = sb + buf * BUFB;
        #pragma unroll
        for (int ks = 0; ks < 2; ++ks) {          // two k16 steps per chunk
            uint32_t ah[2][4], al[2][4], bh[8][2], bl[8][2];
            {
                const int r = lane & 15, cseg = lane >> 4;
                #pragma unroll
                for (int mt = 0; mt < 2; ++mt) {
                    uint32_t off = (uint32_t)(wm0 + mt * 16 + r) * (ASTRIDE * 2) + (ks * 16 + cseg * 8) * 2;
                    ldsm4(ah[mt], base + 0 * MATB + off);
                    ldsm4(al[mt], base + 1 * MATB + off);
                }
            }
            {
                const int r = lane & 7, cs = (lane >> 3) & 1;
                #pragma unroll
                for (int nt = 0; nt < 8; ++nt) {
                    uint32_t off = (uint32_t)(wn0 + nt * 8 + r) * (ASTRIDE * 2) + (ks * 16 + cs * 8) * 2;
                    ldsm2(bh[nt], base + 2 * MATB + off);
                    ldsm2(bl[nt], base + 3 * MATB + off);
                }
            }
            #pragma unroll
            for (int mt = 0; mt < 2; ++mt)
                #pragma unroll
                for (int nt = 0; nt < 8; ++nt) {
                    mma16816(acc[mt][nt], ah[mt], bh[nt]);
                    mma16816(acc[mt][nt], ah[mt], bl[nt]);
                    mma16816(acc[mt][nt], al[mt], bh[nt]);
                }
        }
    };

    const int nc = K / KC;
    do_ldg(0); do_sts(0);
    __syncthreads();
    for (int c = 0; c < nc; ++c) {
        if (c + 1 < nc) do_ldg((c + 1) * KC);
        compute(c & 1);
        if (c + 1 < nc) do_sts((c + 1) & 1);
        __syncthreads();
    }

    #pragma unroll
    for (int mt = 0; mt < 2; ++mt)
        #pragma unroll
        for (int nt = 0; nt < 8; ++nt) {
            int r0 = m0 + wm0 + mt * 16 + (lane >> 2);
            int cc = n0 + wn0 + nt * 8 + (lane & 3) * 2;
            float* p0 = C + (long)r0 * ldc + cc;
            float2 v0 = make_float2(acc[mt][nt][0] * alpha, acc[mt][nt][1] * alpha);
            float2 v1 = make_float2(acc[mt][nt][2] * alpha, acc[mt][nt][3] * alpha);
            *(float2*)p0              = v0;
            *(float2*)(p0 + 8 * ldc) = v1;
        }
}

// ---------------- hi/lo split conversion ----------------
__global__ void cvt2(const float* __restrict__ src, __nv_bfloat16* __restrict__ hi,
                     __nv_bfloat16* __restrict__ lo, int n)
{
    int i = blockIdx.x * blockDim.x + threadIdx.x;
    if (i >= n) return;
    float x = src[i];
    __nv_bfloat16 h = __float2bfloat16(x);
    hi[i] = h;
    lo[i] = __float2bfloat16(x - __bfloat162float(h));
}

// ---------------- RoPE + hi/lo split ----------------
__global__ void rope_cvt(const float* __restrict__ x, const float* __restrict__ cs,
                         const float* __restrict__ sn, __nv_bfloat16* __restrict__ xh,
                         __nv_bfloat16* __restrict__ xl, int nheads)
{
    int idx = blockIdx.x * blockDim.x + threadIdx.x;
    int total = SEQ * nheads * 64;
    if (idx >= total) return;
    int d = idx & 63;
    int rest = idx >> 6;
    int h = rest % nheads;
    int t = rest / nheads;
    long base = ((long)t * nheads + h) * HDIM;
    float x1 = x[base + d], x2 = x[base + d + 64];
    float c1 = cs[t * HDIM + d],      s1 = sn[t * HDIM + d];
    float c2 = cs[t * HDIM + d + 64], s2 = sn[t * HDIM + d + 64];
    float y1 = x1 * c1 - x2 * s1;
    float y2 = x2 * c2 + x1 * s2;
    __nv_bfloat16 h1 = __float2bfloat16(y1);
    __nv_bfloat16 h2 = __float2bfloat16(y2);
    xh[base + d]      = h1; xl[base + d]      = __float2bfloat16(y1 - __bfloat162float(h1));
    xh[base + d + 64] = h2; xl[base + d + 64] = __float2bfloat16(y2 - __bfloat162float(h2));
}

// ---------------- v transpose + hi/lo split: vT[rd][t] = v[t][rd] ----------------
__global__ void vt_cvt(const float* __restrict__ v, __nv_bfloat16* __restrict__ vh,
                       __nv_bfloat16* __restrict__ vl)
{
    int idx = blockIdx.x * blockDim.x + threadIdx.x;
    int rd = idx & 1023;
    int t  = idx >> 10;
    float x = v[(long)t * 1024 + rd];
    __nv_bfloat16 h = __float2bfloat16(x);
    long o = (long)rd * SEQ + t;
    vh[o] = h;
    vl[o] = __float2bfloat16(x - __bfloat162float(h));
}

// ---------------- block reductions (blockDim.x == 256) ----------------
__device__ __forceinline__ int blockSumI(int v) {
    __shared__ int sm[8];
    int lane = threadIdx.x & 31, wid = threadIdx.x >> 5;
    #pragma unroll
    for (int o = 16; o; o >>= 1) v += __shfl_xor_sync(0xffffffffu, v, o);
    if (lane == 0) sm[wid] = v;
    __syncthreads();
    if (wid == 0) {
        int x = (lane < 8) ? sm[lane] : 0;
        #pragma unroll
        for (int o = 16; o; o >>= 1) x += __shfl_xor_sync(0xffffffffu, x, o);
        if (lane == 0) sm[0] = x;
    }
    __syncthreads();
    v = sm[0];
    __syncthreads();
    return v;
}
__device__ __forceinline__ float blockSumF(float v) {
    __shared__ float sm[8];
    int lane = threadIdx.x & 31, wid = threadIdx.x >> 5;
    #pragma unroll
    for (int o = 16; o; o >>= 1) v += __shfl_xor_sync(0xffffffffu, v, o);
    if (lane == 0) sm[wid] = v;
    __syncthreads();
    if (wid == 0) {
        float x = (lane < 8) ? sm[lane] : 0.0f;
        #pragma unroll
        for (int o = 16; o; o >>= 1) x += __shfl_xor_sync(0xffffffffu, x, o);
        if (lane == 0) sm[0] = x;
    }
    __syncthreads();
    v = sm[0];
    __syncthreads();
    return v;
}
__device__ __forceinline__ float blockMaxF(float v) {
    __shared__ float sm[8];
    int lane = threadIdx.x & 31, wid = threadIdx.x >> 5;
    #pragma unroll
    for (int o = 16; o; o >>= 1) v = fmaxf(v, __shfl_xor_sync(0xffffffffu, v, o));
    if (lane == 0) sm[wid] = v;
    __syncthreads();
    if (wid == 0) {
        float x = (lane < 8) ? sm[lane] : -3.0e38f;
        #pragma unroll
        for (int o = 16; o; o >>= 1) x = fmaxf(x, __shfl_xor_sync(0xffffffffu, x, o));
        if (lane == 0) sm[0] = x;
    }
    __syncthreads();
    v = sm[0];
    __syncthreads();
    return v;
}

// ---------------- stats: head-0 causal row max ----------------
__global__ __launch_bounds__(256)
void row_max0(const float* __restrict__ scores, float* __restrict__ max0)
{
    int t = blockIdx.x;
    int L = t + 1;
    const float* row = scores + ((size_t)t << 10);
    float m = -3.0e38f;
    for (int j = threadIdx.x; j < L; j += 256) m = fmaxf(m, row[j]);
    m = blockMaxF(m);
    if (threadIdx.x == 0) max0[t] = m;
}

// ---------------- stats: fetch_num[t] = min(204, (sum_h count_h) >> 5) ----------------
__global__ __launch_bounds__(256)
void fetch_kernel(const float* __restrict__ scores, const float* __restrict__ max0,
                  int* __restrict__ fetch)
{
    int t = blockIdx.x;
    int L = t + 1;
    float thr = max0[t] - ALPHA_M;
    int c = 0;
    for (int h = 0; h < NHEADS; ++h) {
        const float* row = scores + ((size_t)h << 20) + ((size_t)t << 10);
        for (int j = threadIdx.x; j < L; j += 256) c += (row[j] >= thr);
    }
    c = blockSumI(c);
    if (threadIdx.x == 0) fetch[t] = min(FETCHMAX, c >> 5);
}

// ---------------- masked softmax (exact top-k radix select) -> probs hi/lo bf16 ----------------
__global__ __launch_bounds__(256)
void mask_softmax(const float* __restrict__ scores, const int* __restrict__ fetch,
                  __nv_bfloat16* __restrict__ ph, __nv_bfloat16* __restrict__ pl)
{
    int t = blockIdx.x, h = blockIdx.y;
    size_t rowoff = ((size_t)h << 20) + ((size_t)t << 10);
    const float* row = scores + rowoff;

    __shared__ float    sr[SEQ];
    __shared__ unsigned su[SEQ];

    int tid = threadIdx.x;

    bool select = (t >= FETCHMAX);
    int kk = 0;
    if (select) {
        kk = fetch[t];
        if (kk <= 0) select = false;
    }
    int L = (t < FETCHMAX) ? (t + 1) : (select ? (t + 1) : SEQ);

    float lm = -3.0e38f;
    for (int j = tid; j < L; j += 256) {
        float s = row[j];
        sr[j] = s;
        unsigned u = __float_as_uint(s);
        u = (u & 0x80000000u) ? ~u : (u | 0x80000000u);
        su[j] = u;
        lm = fmaxf(lm, s);
    }
    __syncthreads();
    float m = blockMaxF(lm);

    unsigned vk = 0;
    int ties = 0;
    bool simple = true;
    if (select) {
        int k = kk;
        unsigned prefix = 0;
        for (int bit = 31; bit >= 0; --bit) {
            unsigned tgt = (prefix >> bit) | 1u;
            int c = 0;
            for (int j = tid; j < L; j += 256) c += ((su[j] >> bit) == tgt);
            c = blockSumI(c);
            if (c >= k) prefix |= (1u << bit);
            else        k -= c;
        }
        vk = prefix;
        ties = k;
        int ce = 0;
        for (int j = tid; j < L; j += 256) ce += (su[j] == vk);
        ce = blockSumI(ce);
        simple = (ce == ties);
    }

    float ls = 0.0f;
    for (int j = tid; j < L; j += 256) {
        bool kept = true;
        if (select) {
            unsigned u = su[j];
            if (u > vk)      kept = true;
            else if (u < vk) kept = false;
            else if (simple) kept = true;
            else {
                int r = 0;
                for (int j2 = 0; j2 < j; ++j2) r += (su[j2] == vk);
                kept = (r < ties);
            }
        }
        float e = kept ? expf(sr[j] - m) : 0.0f;
        sr[j] = e;
        ls += e;
    }
    float Z = blockSumF(ls);
    float inv = 1.0f / Z;
    for (int j = tid; j < SEQ; j += 256) {
        float p = (j < L) ? sr[j] * inv : 0.0f;
        __nv_bfloat16 hh = __float2bfloat16(p);
        ph[rowoff + j] = hh;
        pl[rowoff + j] = __float2bfloat16(p - __bfloat162float(hh));
    }
}

// ---------------- launch ----------------
extern "C" void kernel_launch(void* const* d_in, const int* in_sizes, int n_in,
                              void* d_out, int out_size)
{
    const float* hs = (const float*)d_in[0];
    const float* cs = (const float*)d_in[1];
    const float* sn = (const float*)d_in[2];
    const float* Wq = (const float*)d_in[3];
    const float* Wk = (const float*)d_in[4];
    const float* Wv = (const float*)d_in[5];
    const float* Wo = (const float*)d_in[6];
    float* out = (float*)d_out;

    float *qp, *kp, *vp, *sp, *ap, *m0p; int* fp;
    __nv_bfloat16 *hsh, *hsl, *Wqh, *Wql, *Wkh, *Wkl, *Wvh, *Wvl, *Woh, *Wol;
    __nv_bfloat16 *qh, *ql, *kh, *kl, *vTh, *vTl, *ph, *pl, *ah, *al;
    cudaGetSymbolAddress((void**)&qp,  g_q);
    cudaGetSymbolAddress((void**)&kp,  g_k);
    cudaGetSymbolAddress((void**)&vp,  g_v);
    cudaGetSymbolAddress((void**)&sp,  g_scores);
    cudaGetSymbolAddress((void**)&ap,  g_attn);
    cudaGetSymbolAddress((void**)&m0p, g_max0);
    cudaGetSymbolAddress((void**)&fp,  g_fetch);
    cudaGetSymbolAddress((void**)&hsh, g_hsh); cudaGetSymbolAddress((void**)&hsl, g_hsl);
    cudaGetSymbolAddress((void**)&Wqh, g_Wqh); cudaGetSymbolAddress((void**)&Wql, g_Wql);
    cudaGetSymbolAddress((void**)&Wkh, g_Wkh); cudaGetSymbolAddress((void**)&Wkl, g_Wkl);
    cudaGetSymbolAddress((void**)&Wvh, g_Wvh); cudaGetSymbolAddress((void**)&Wvl, g_Wvl);
    cudaGetSymbolAddress((void**)&Woh, g_Woh); cudaGetSymbolAddress((void**)&Wol, g_Wol);
    cudaGetSymbolAddress((void**)&qh,  g_qh);  cudaGetSymbolAddress((void**)&ql,  g_ql);
    cudaGetSymbolAddress((void**)&kh,  g_kh);  cudaGetSymbolAddress((void**)&kl,  g_kl);
    cudaGetSymbolAddress((void**)&vTh, g_vTh); cudaGetSymbolAddress((void**)&vTl, g_vTl);
    cudaGetSymbolAddress((void**)&ph,  g_ph);  cudaGetSymbolAddress((void**)&pl,  g_pl);
    cudaGetSymbolAddress((void**)&ah,  g_ah);  cudaGetSymbolAddress((void**)&al,  g_al);

    cudaFuncSetAttribute(gemm_mma, cudaFuncAttributeMaxDynamicSharedMemorySize, GEMM_SMEM);

    const int NHS = SEQ * DMODEL;
    const int NWQ = DMODEL * DMODEL;
    const int NWK = NKV * HDIM * DMODEL;

    // hi/lo splits of inputs
    cvt2<<<NHS / 256, 256>>>(hs, hsh, hsl, NHS);
    cvt2<<<NWQ / 256, 256>>>(Wq, Wqh, Wql, NWQ);
    cvt2<<<NWK / 256, 256>>>(Wk, Wkh, Wkl, NWK);
    cvt2<<<NWK / 256, 256>>>(Wv, Wvh, Wvl, NWK);
    cvt2<<<NWQ / 256, 256>>>(Wo, Woh, Wol, NWQ);

    // QKV projections (BT): C = X @ W^T
    gemm_mma<<<dim3(32, 8, 1), 256, GEMM_SMEM>>>(hsh, hsl, Wqh, Wql, qp, DMODEL,
        DMODEL, DMODEL, DMODEL, 0, 0, 0, 1, 1.0f);
    gemm_mma<<<dim3(8, 8, 1), 256, GEMM_SMEM>>>(hsh, hsl, Wkh, Wkl, kp, DMODEL,
        DMODEL, DMODEL, NKV * HDIM, 0, 0, 0, 1, 1.0f);
    gemm_mma<<<dim3(8, 8, 1), 256, GEMM_SMEM>>>(hsh, hsl, Wvh, Wvl, vp, DMODEL,
        DMODEL, DMODEL, NKV * HDIM, 0, 0, 0, 1, 1.0f);

    // RoPE + split; v transpose + split
    rope_cvt<<<(SEQ * NHEADS * 64) / 256, 256>>>(qp, cs, sn, qh, ql, NHEADS);
    rope_cvt<<<(SEQ * NKV * 64) / 256, 256>>>(kp, cs, sn, kh, kl, NKV);
    vt_cvt<<<(SEQ * NKV * HDIM) / 256, 256>>>(vp, vTh, vTl);

    // scores[h] = scaling * q_h @ k_{h/4}^T  (batched, GQA)
    gemm_mma<<<dim3(8, 8, NHEADS), 256, GEMM_SMEM>>>(qh, ql, kh, kl, sp, HDIM,
        DMODEL, NKV * HDIM, SEQ, /*sA=*/HDIM, /*sB=*/HDIM, /*sC=*/(long)SEQ * SEQ, 4, SCALING);

    // dynamic mask stats + masked softmax (emits probs hi/lo)
    row_max0<<<SEQ, 256>>>(sp, m0p);
    fetch_kernel<<<SEQ, 256>>>(sp, m0p, fp);
    mask_softmax<<<dim3(SEQ, NHEADS), 256>>>(sp, fp, ph, pl);

    // attn[h] = probs_h @ v_{h/4}  (B = vT, BT form; N=128)
    gemm_mma<<<dim3(1, 8, NHEADS), 256, GEMM_SMEM>>>(ph, pl, vTh, vTl, ap, SEQ,
        SEQ, SEQ, DMODEL, /*sA=*/(long)SEQ * SEQ, /*sB=*/(long)HDIM * SEQ, /*sC=*/HDIM, 4, 1.0f);

    // split attn, then output projection
    cvt2<<<NHS / 256, 256>>>(ap, ah, al, NHS);
    gemm_mma<<<dim3(32, 8, 1), 256, GEMM_SMEM>>>(ah, al, Woh, Wol, out, DMODEL,
        DMODEL, DMODEL, DMODEL, 0, 0, 0, 1, 1.0f);
}

// round 15
// speedup vs baseline: 2.1654x; 1.0926x over previous
#include <cuda_runtime.h>
#include <cuda_bf16.h>
#include <math.h>
#include <stdint.h>

#define SEQ      1024
#define DMODEL   4096
#define NHEADS   32
#define NKV      8
#define HDIM     128
#define FETCHMAX 204
#define ALPHA_M  5.0f
#define SCALING  0.08838834764831845f

// ---------------- device scratch (no allocations allowed) ----------------
__device__ float g_q[SEQ * DMODEL];
__device__ float g_k[SEQ * NKV * HDIM];
__device__ float g_v[SEQ * NKV * HDIM];
__device__ float g_scores[33554432];          // 128 MB fp32 scores
__device__ float g_max0[SEQ];
__device__ int   g_fetch[SEQ];

__device__ __nv_bfloat16 g_hsh[SEQ * DMODEL],  g_hsl[SEQ * DMODEL];
__device__ __nv_bfloat16 g_Wqh[DMODEL * DMODEL], g_Wql[DMODEL * DMODEL];
__device__ __nv_bfloat16 g_Wkh[NKV * HDIM * DMODEL], g_Wkl[NKV * HDIM * DMODEL];
__device__ __nv_bfloat16 g_Wvh[NKV * HDIM * DMODEL], g_Wvl[NKV * HDIM * DMODEL];
__device__ __nv_bfloat16 g_Woh[DMODEL * DMODEL], g_Wol[DMODEL * DMODEL];
__device__ __nv_bfloat16 g_qh[SEQ * DMODEL],   g_ql[SEQ * DMODEL];
__device__ __nv_bfloat16 g_kh[SEQ * NKV * HDIM], g_kl[SEQ * NKV * HDIM];
__device__ __nv_bfloat16 g_vTh[NKV * HDIM * SEQ], g_vTl[NKV * HDIM * SEQ];
__device__ __nv_bfloat16 g_ph[33554432], g_pl[33554432];
__device__ __nv_bfloat16 g_ah[SEQ * DMODEL],  g_al[SEQ * DMODEL];

// ---------------- PTX helpers (arch-agnostic: ldmatrix + mma.sync + cp.async, sm_80+) ----------------
__device__ __forceinline__ uint32_t smem_u32(const void* p) {
    uint32_t a;
    asm("{ .reg .u64 t; cvta.to.shared.u64 t, %1; cvt.u32.u64 %0, t; }" : "=r"(a) : "l"(p));
    return a;
}
__device__ __forceinline__ void ldsm4(uint32_t* r, uint32_t a) {
    asm volatile("ldmatrix.sync.aligned.m8n8.x4.shared.b16 {%0,%1,%2,%3}, [%4];"
        : "=r"(r[0]), "=r"(r[1]), "=r"(r[2]), "=r"(r[3]) : "r"(a));
}
__device__ __forceinline__ void ldsm2(uint32_t* r, uint32_t a) {
    asm volatile("ldmatrix.sync.aligned.m8n8.x2.shared.b16 {%0,%1}, [%2];"
        : "=r"(r[0]), "=r"(r[1]) : "r"(a));
}
__device__ __forceinline__ void mma16816(float* c, const uint32_t* a, const uint32_t* b) {
    asm volatile("mma.sync.aligned.m16n8k16.row.col.f32.bf16.bf16.f32 "
        "{%0,%1,%2,%3}, {%4,%5,%6,%7}, {%8,%9}, {%0,%1,%2,%3};"
        : "+f"(c[0]), "+f"(c[1]), "+f"(c[2]), "+f"(c[3])
        : "r"(a[0]), "r"(a[1]), "r"(a[2]), "r"(a[3]), "r"(b[0]), "r"(b[1]));
}
__device__ __forceinline__ void cpasync16(uint32_t dst, const void* src) {
    asm volatile("cp.async.cg.shared.global [%0], [%1], 16;" :: "r"(dst), "l"(src));
}
#define CP_COMMIT() asm volatile("cp.async.commit_group;" ::: "memory")
#define CP_WAIT(n)  asm volatile("cp.async.wait_group %0;" :: "n"(n) : "memory")

// ---------------- bf16x3 BT GEMM via mma.sync + cp.async ----------------
// C[m,n] = alpha * sum_k A[m,k]*B[n,k]; A,B hi/lo bf16, K-major.
// 128x128 CTA tile, KC=32 chunks, 2-stage cp.async pipeline, 2 CTAs/SM.
// causal: skip tiles with blockIdx.x > blockIdx.y (scores upper triangle).
// kcap:   limit K to m0+128 (PV: probs rows zero beyond diagonal).
// Ch/Cl non-null: write hi/lo bf16 split instead of fp32 C.
#define KC       32
#define ASTRIDE  40                     // halves per SMEM row (32 + 8 pad)
#define ROWB     (ASTRIDE * 2)          // 80 B
#define MATB     (128 * ROWB)           // 10240 B per matrix tile
#define BUFB     (4 * MATB)             // Ah, Al, Bh, Bl
#define GEMM_SMEM (2 * BUFB)            // 81920 B double-buffered

__global__ __launch_bounds__(256, 2)
void gemm_mma(const __nv_bfloat16* __restrict__ Ah, const __nv_bfloat16* __restrict__ Al,
              const __nv_bfloat16* __restrict__ Bh, const __nv_bfloat16* __restrict__ Bl,
              float* __restrict__ C, __nv_bfloat16* __restrict__ Ch, __nv_bfloat16* __restrict__ Cl,
              int K, int lda, int ldb, int ldc,
              long sA, long sB, long sC, int zdivB, float alpha, int causal, int kcap)
{
    if (causal && blockIdx.x > blockIdx.y) return;
    extern __shared__ char smem[];
    const uint32_t sb = smem_u32(smem);
    const int tid = threadIdx.x, wid = tid >> 5, lane = tid & 31;
    const int z = blockIdx.z;
    Ah += (long)z * sA; Al += (long)z * sA;
    Bh += (long)(z / zdivB) * sB; Bl += (long)(z / zdivB) * sB;
    const int m0 = blockIdx.y * 128, n0 = blockIdx.x * 128;
    const int wm0 = (wid & 3) * 32, wn0 = (wid >> 2) * 64;

    const int Ke = kcap ? min(K, m0 + 128) : K;
    const int nc = Ke / KC;

    float acc[2][8][4];
    #pragma unroll
    for (int mt = 0; mt < 2; ++mt)
        #pragma unroll
        for (int nt = 0; nt < 8; ++nt)
            #pragma unroll
            for (int i = 0; i < 4; ++i) acc[mt][nt][i] = 0.0f;

    const __nv_bfloat16* srcs[4] = { Ah, Al, Bh, Bl };
    const int lds[4]  = { lda, lda, ldb, ldb };
    const int rowb[4] = { m0, m0, n0, n0 };

    // one chunk load: 512 x 16B per matrix tile quartet, 8 cp.asyncs per thread
    auto load = [&](int c, int buf) {
        const int k0 = c * KC;
        #pragma unroll
        for (int t = 0; t < 4; ++t) {
            const uint32_t tb = sb + buf * BUFB + t * MATB;
            #pragma unroll
            for (int i = 0; i < 2; ++i) {
                int seg = i * 256 + tid;          // 512 segs = 128 rows x 4 x 16B
                int row = seg >> 2, cs4 = seg & 3;
                cpasync16(tb + row * ROWB + cs4 * 16,
                          srcs[t] + (long)(rowb[t] + row) * lds[t] + k0 + cs4 * 8);
            }
        }
    };

    auto compute = [&](int buf) {
        const uint32_t base = sb + buf * BUFB;
        #pragma unroll
        for (int ks = 0; ks < 2; ++ks) {
            uint32_t ah[2][4], al[2][4];
            {
                const int r = lane & 15, cseg = lane >> 4;
                #pragma unroll
                for (int mt = 0; mt < 2; ++mt) {
                    uint32_t off = (uint32_t)(wm0 + mt * 16 + r) * ROWB + (ks * 16 + cseg * 8) * 2;
                    ldsm4(ah[mt], base + 0 * MATB + off);
                    ldsm4(al[mt], base + 1 * MATB + off);
                }
            }
            const int rB = lane & 7, cB = (lane >> 3) & 1;
            #pragma unroll
            for (int nt = 0; nt < 8; ++nt) {      // B frags loaded just-in-time (low reg pressure)
                uint32_t bh[2], bl[2];
                uint32_t off = (uint32_t)(wn0 + nt * 8 + rB) * ROWB + (ks * 16 + cB * 8) * 2;
                ldsm2(bh, base + 2 * MATB + off);
                ldsm2(bl, base + 3 * MATB + off);
                #pragma unroll
                for (int mt = 0; mt < 2; ++mt) {
                    mma16816(acc[mt][nt], ah[mt], bh);
                    mma16816(acc[mt][nt], ah[mt], bl);
                    mma16816(acc[mt][nt], al[mt], bh);
                }
            }
        }
    };

    load(0, 0); CP_COMMIT();
    load(1, 1); CP_COMMIT();
    for (int c = 0; c < nc; ++c) {
        if (c == nc - 1) { CP_WAIT(0); } else { CP_WAIT(1); }
        __syncthreads();
        compute(c & 1);
        if (c + 2 < nc) {
            __syncthreads();                      // buf c&1 fully consumed by all warps
            load(c + 2, c & 1); CP_COMMIT();
        }
    }

    const long cz = (long)z * sC;
    #pragma unroll
    for (int mt = 0; mt < 2; ++mt)
        #pragma unroll
        for (int nt = 0; nt < 8; ++nt) {
            int r0 = m0 + wm0 + mt * 16 + (lane >> 2);
            int cc = n0 + wn0 + nt * 8 + (lane & 3) * 2;
            if (Ch) {
                #pragma unroll
                for (int hrow = 0; hrow < 2; ++hrow) {
                    float a0 = acc[mt][nt][hrow * 2 + 0] * alpha;
                    float a1 = acc[mt][nt][hrow * 2 + 1] * alpha;
                    __nv_bfloat16 h0 = __float2bfloat16(a0), h1 = __float2bfloat16(a1);
                    __nv_bfloat16 l0 = __float2bfloat16(a0 - __bfloat162float(h0));
                    __nv_bfloat16 l1 = __float2bfloat16(a1 - __bfloat162float(h1));
                    long off = cz + (long)(r0 + hrow * 8) * ldc + cc;
                    *(__nv_bfloat162*)(Ch + off) = __halves2bfloat162(h0, h1);
                    *(__nv_bfloat162*)(Cl + off) = __halves2bfloat162(l0, l1);
                }
            } else {
                float* p0 = C + cz + (long)r0 * ldc + cc;
                *(float2*)p0             = make_float2(acc[mt][nt][0] * alpha, acc[mt][nt][1] * alpha);
                *(float2*)(p0 + 8 * ldc) = make_float2(acc[mt][nt][2] * alpha, acc[mt][nt][3] * alpha);
            }
        }
}

// ---------------- vectorized hi/lo split: 4 floats/thread ----------------
__global__ void cvt2v(const float4* __restrict__ src, uint2* __restrict__ hi,
                      uint2* __restrict__ lo, int n4)
{
    int i = blockIdx.x * blockDim.x + threadIdx.x;
    if (i >= n4) return;
    float4 x = src[i];
    __nv_bfloat16 h0 = __float2bfloat16(x.x), h1 = __float2bfloat16(x.y);
    __nv_bfloat16 h2 = __float2bfloat16(x.z), h3 = __float2bfloat16(x.w);
    __nv_bfloat16 l0 = __float2bfloat16(x.x - __bfloat162float(h0));
    __nv_bfloat16 l1 = __float2bfloat16(x.y - __bfloat162float(h1));
    __nv_bfloat16 l2 = __float2bfloat16(x.z - __bfloat162float(h2));
    __nv_bfloat16 l3 = __float2bfloat16(x.w - __bfloat162float(h3));
    union { __nv_bfloat162 b[2]; uint2 u; } H, L;
    H.b[0] = __halves2bfloat162(h0, h1); H.b[1] = __halves2bfloat162(h2, h3);
    L.b[0] = __halves2bfloat162(l0, l1); L.b[1] = __halves2bfloat162(l2, l3);
    hi[i] = H.u;
    lo[i] = L.u;
}

// ---------------- RoPE + hi/lo split ----------------
__global__ void rope_cvt(const float* __restrict__ x, const float* __restrict__ cs,
                         const float* __restrict__ sn, __nv_bfloat16* __restrict__ xh,
                         __nv_bfloat16* __restrict__ xl, int nheads)
{
    int idx = blockIdx.x * blockDim.x + threadIdx.x;
    int total = SEQ * nheads * 64;
    if (idx >= total) return;
    int d = idx & 63;
    int rest = idx >> 6;
    int h = rest % nheads;
    int t = rest / nheads;
    long base = ((long)t * nheads + h) * HDIM;
    float x1 = x[base + d], x2 = x[base + d + 64];
    float c1 = cs[t * HDIM + d],      s1 = sn[t * HDIM + d];
    float c2 = cs[t * HDIM + d + 64], s2 = sn[t * HDIM + d + 64];
    float y1 = x1 * c1 - x2 * s1;
    float y2 = x2 * c2 + x1 * s2;
    __nv_bfloat16 h1 = __float2bfloat16(y1);
    __nv_bfloat16 h2 = __float2bfloat16(y2);
    xh[base + d]      = h1; xl[base + d]      = __float2bfloat16(y1 - __bfloat162float(h1));
    xh[base + d + 64] = h2; xl[base + d + 64] = __float2bfloat16(y2 - __bfloat162float(h2));
}

// ---------------- v transpose + hi/lo split ----------------
__global__ void vt_cvt(const float* __restrict__ v, __nv_bfloat16* __restrict__ vh,
                       __nv_bfloat16* __restrict__ vl)
{
    int idx = blockIdx.x * blockDim.x + threadIdx.x;
    int rd = idx & 1023;
    int t  = idx >> 10;
    float x = v[(long)t * 1024 + rd];
    __nv_bfloat16 h = __float2bfloat16(x);
    long o = (long)rd * SEQ + t;
    vh[o] = h;
    vl[o] = __float2bfloat16(x - __bfloat162float(h));
}

// ---------------- block reductions (blockDim.x == 256) ----------------
__device__ __forceinline__ int blockSumI(int v) {
    __shared__ int sm[8];
    int lane = threadIdx.x & 31, wid = threadIdx.x >> 5;
    #pragma unroll
    for (int o = 16; o; o >>= 1) v += __shfl_xor_sync(0xffffffffu, v, o);
    if (lane == 0) sm[wid] = v;
    __syncthreads();
    if (wid == 0) {
        int x = (lane < 8) ? sm[lane] : 0;
        #pragma unroll
        for (int o = 16; o; o >>= 1) x += __shfl_xor_sync(0xffffffffu, x, o);
        if (lane == 0) sm[0] = x;
    }
    __syncthreads();
    v = sm[0];
    __syncthreads();
    return v;
}
__device__ __forceinline__ float blockSumF(float v) {
    __shared__ float sm[8];
    int lane = threadIdx.x & 31, wid = threadIdx.x >> 5;
    #pragma unroll
    for (int o = 16; o; o >>= 1) v += __shfl_xor_sync(0xffffffffu, v, o);
    if (lane == 0) sm[wid] = v;
    __syncthreads();
    if (wid == 0) {
        float x = (lane < 8) ? sm[lane] : 0.0f;
        #pragma unroll
        for (int o = 16; o; o >>= 1) x += __shfl_xor_sync(0xffffffffu, x, o);
        if (lane == 0) sm[0] = x;
    }
    __syncthreads();
    v = sm[0];
    __syncthreads();
    return v;
}
__device__ __forceinline__ float blockMaxF(float v) {
    __shared__ float sm[8];
    int lane = threadIdx.x & 31, wid = threadIdx.x >> 5;
    #pragma unroll
    for (int o = 16; o; o >>= 1) v = fmaxf(v, __shfl_xor_sync(0xffffffffu, v, o));
    if (lane == 0) sm[wid] = v;
    __syncthreads();
    if (wid == 0) {
        float x = (lane < 8) ? sm[lane] : -3.0e38f;
        #pragma unroll
        for (int o = 16; o; o >>= 1) x = fmaxf(x, __shfl_xor_sync(0xffffffffu, x, o));
        if (lane == 0) sm[0] = x;
    }
    __syncthreads();
    v = sm[0];
    __syncthreads();
    return v;
}

// ---------------- stats: head-0 causal row max ----------------
__global__ __launch_bounds__(256)
void row_max0(const float* __restrict__ scores, float* __restrict__ max0)
{
    int t = blockIdx.x;
    int L = t + 1;
    const float* row = scores + ((size_t)t << 10);
    float m = -3.0e38f;
    for (int j = threadIdx.x; j < L; j += 256) m = fmaxf(m, row[j]);
    m = blockMaxF(m);
    if (threadIdx.x == 0) max0[t] = m;
}

// ---------------- stats: fetch_num[t] = min(204, (sum_h count_h) >> 5) ----------------
__global__ __launch_bounds__(256)
void fetch_kernel(const float* __restrict__ scores, const float* __restrict__ max0,
                  int* __restrict__ fetch)
{
    int t = blockIdx.x;
    int L = t + 1;
    float thr = max0[t] - ALPHA_M;
    int c = 0;
    for (int h = 0; h < NHEADS; ++h) {
        const float* row = scores + ((size_t)h << 20) + ((size_t)t << 10);
        for (int j = threadIdx.x; j < L; j += 256) c += (row[j] >= thr);
    }
    c = blockSumI(c);
    if (threadIdx.x == 0) fetch[t] = min(FETCHMAX, c >> 5);
}

// ---------------- masked softmax (exact top-k radix select) -> probs hi/lo bf16 ----------------
__global__ __launch_bounds__(256)
void mask_softmax(const float* __restrict__ scores, const int* __restrict__ fetch,
                  __nv_bfloat16* __restrict__ ph, __nv_bfloat16* __restrict__ pl)
{
    int t = blockIdx.x, h = blockIdx.y;
    size_t rowoff = ((size_t)h << 20) + ((size_t)t << 10);
    const float* row = scores + rowoff;

    __shared__ float    sr[SEQ];
    __shared__ unsigned su[SEQ];

    int tid = threadIdx.x;

    bool select = (t >= FETCHMAX);
    int kk = 0;
    if (select) {
        kk = fetch[t];
        if (kk <= 0) select = false;
    }
    int L = (t < FETCHMAX) ? (t + 1) : (select ? (t + 1) : SEQ);

    float lm = -3.0e38f;
    for (int j = tid; j < L; j += 256) {
        float s = row[j];
        sr[j] = s;
        unsigned u = __float_as_uint(s);
        u = (u & 0x80000000u) ? ~u : (u | 0x80000000u);
        su[j] = u;
        lm = fmaxf(lm, s);
    }
    __syncthreads();
    float m = blockMaxF(lm);

    unsigned vk = 0;
    int ties = 0;
    bool simple = true;
    if (select) {
        int k = kk;
        unsigned prefix = 0;
        for (int bit = 31; bit >= 0; --bit) {
            unsigned tgt = (prefix >> bit) | 1u;
            int c = 0;
            for (int j = tid; j < L; j += 256) c += ((su[j] >> bit) == tgt);
            c = blockSumI(c);
            if (c >= k) prefix |= (1u << bit);
            else        k -= c;
        }
        vk = prefix;
        ties = k;
        int ce = 0;
        for (int j = tid; j < L; j += 256) ce += (su[j] == vk);
        ce = blockSumI(ce);
        simple = (ce == ties);
    }

    float ls = 0.0f;
    for (int j = tid; j < L; j += 256) {
        bool kept = true;
        if (select) {
            unsigned u = su[j];
            if (u > vk)      kept = true;
            else if (u < vk) kept = false;
            else if (simple) kept = true;
            else {
                int r = 0;
                for (int j2 = 0; j2 < j; ++j2) r += (su[j2] == vk);
                kept = (r < ties);
            }
        }
        float e = kept ? expf(sr[j] - m) : 0.0f;
        sr[j] = e;
        ls += e;
    }
    float Z = blockSumF(ls);
    float inv = 1.0f / Z;
    for (int j = tid; j < SEQ; j += 256) {
        float p = (j < L) ? sr[j] * inv : 0.0f;
        __nv_bfloat16 hh = __float2bfloat16(p);
        ph[rowoff + j] = hh;
        pl[rowoff + j] = __float2bfloat16(p - __bfloat162float(hh));
    }
}

// ---------------- launch ----------------
extern "C" void kernel_launch(void* const* d_in, const int* in_sizes, int n_in,
                              void* d_out, int out_size)
{
    const float* hs = (const float*)d_in[0];
    const float* cs = (const float*)d_in[1];
    const float* sn = (const float*)d_in[2];
    const float* Wq = (const float*)d_in[3];
    const float* Wk = (const float*)d_in[4];
    const float* Wv = (const float*)d_in[5];
    const float* Wo = (const float*)d_in[6];
    float* out = (float*)d_out;

    float *qp, *kp, *vp, *sp, *m0p; int* fp;
    __nv_bfloat16 *hsh, *hsl, *Wqh, *Wql, *Wkh, *Wkl, *Wvh, *Wvl, *Woh, *Wol;
    __nv_bfloat16 *qh, *ql, *kh, *kl, *vTh, *vTl, *ph, *pl, *ah, *al;
    cudaGetSymbolAddress((void**)&qp,  g_q);
    cudaGetSymbolAddress((void**)&kp,  g_k);
    cudaGetSymbolAddress((void**)&vp,  g_v);
    cudaGetSymbolAddress((void**)&sp,  g_scores);
    cudaGetSymbolAddress((void**)&m0p, g_max0);
    cudaGetSymbolAddress((void**)&fp,  g_fetch);
    cudaGetSymbolAddress((void**)&hsh, g_hsh); cudaGetSymbolAddress((void**)&hsl, g_hsl);
    cudaGetSymbolAddress((void**)&Wqh, g_Wqh); cudaGetSymbolAddress((void**)&Wql, g_Wql);
    cudaGetSymbolAddress((void**)&Wkh, g_Wkh); cudaGetSymbolAddress((void**)&Wkl, g_Wkl);
    cudaGetSymbolAddress((void**)&Wvh, g_Wvh); cudaGetSymbolAddress((void**)&Wvl, g_Wvl);
    cudaGetSymbolAddress((void**)&Woh, g_Woh); cudaGetSymbolAddress((void**)&Wol, g_Wol);
    cudaGetSymbolAddress((void**)&qh,  g_qh);  cudaGetSymbolAddress((void**)&ql,  g_ql);
    cudaGetSymbolAddress((void**)&kh,  g_kh);  cudaGetSymbolAddress((void**)&kl,  g_kl);
    cudaGetSymbolAddress((void**)&vTh, g_vTh); cudaGetSymbolAddress((void**)&vTl, g_vTl);
    cudaGetSymbolAddress((void**)&ph,  g_ph);  cudaGetSymbolAddress((void**)&pl,  g_pl);
    cudaGetSymbolAddress((void**)&ah,  g_ah);  cudaGetSymbolAddress((void**)&al,  g_al);

    cudaFuncSetAttribute(gemm_mma, cudaFuncAttributeMaxDynamicSharedMemorySize, GEMM_SMEM);

    const int NHS = SEQ * DMODEL;
    const int NWQ = DMODEL * DMODEL;
    const int NWK = NKV * HDIM * DMODEL;

    // hi/lo splits of inputs (vectorized, 4 elem/thread)
    cvt2v<<<NHS / 1024, 256>>>((const float4*)hs, (uint2*)hsh, (uint2*)hsl, NHS / 4);
    cvt2v<<<NWQ / 1024, 256>>>((const float4*)Wq, (uint2*)Wqh, (uint2*)Wql, NWQ / 4);
    cvt2v<<<NWK / 1024, 256>>>((const float4*)Wk, (uint2*)Wkh, (uint2*)Wkl, NWK / 4);
    cvt2v<<<NWK / 1024, 256>>>((const float4*)Wv, (uint2*)Wvh, (uint2*)Wvl, NWK / 4);
    cvt2v<<<NWQ / 1024, 256>>>((const float4*)Wo, (uint2*)Woh, (uint2*)Wol, NWQ / 4);

    // QKV projections (BT): C = X @ W^T
    gemm_mma<<<dim3(32, 8, 1), 256, GEMM_SMEM>>>(hsh, hsl, Wqh, Wql, qp, nullptr, nullptr,
        DMODEL, DMODEL, DMODEL, DMODEL, 0, 0, 0, 1, 1.0f, 0, 0);
    gemm_mma<<<dim3(8, 8, 1), 256, GEMM_SMEM>>>(hsh, hsl, Wkh, Wkl, kp, nullptr, nullptr,
        DMODEL, DMODEL, DMODEL, NKV * HDIM, 0, 0, 0, 1, 1.0f, 0, 0);
    gemm_mma<<<dim3(8, 8, 1), 256, GEMM_SMEM>>>(hsh, hsl, Wvh, Wvl, vp, nullptr, nullptr,
        DMODEL, DMODEL, DMODEL, NKV * HDIM, 0, 0, 0, 1, 1.0f, 0, 0);

    // RoPE + split; v transpose + split
    rope_cvt<<<(SEQ * NHEADS * 64) / 256, 256>>>(qp, cs, sn, qh, ql, NHEADS);
    rope_cvt<<<(SEQ * NKV * 64) / 256, 256>>>(kp, cs, sn, kh, kl, NKV);
    vt_cvt<<<(SEQ * NKV * HDIM) / 256, 256>>>(vp, vTh, vTl);

    // scores[h] = scaling * q_h @ k_{h/4}^T  (batched, GQA, causal tile-skip)
    gemm_mma<<<dim3(8, 8, NHEADS), 256, GEMM_SMEM>>>(qh, ql, kh, kl, sp, nullptr, nullptr,
        HDIM, DMODEL, NKV * HDIM, SEQ, /*sA=*/HDIM, /*sB=*/HDIM, /*sC=*/(long)SEQ * SEQ, 4,
        SCALING, /*causal=*/1, 0);

    // dynamic mask stats + masked softmax (emits probs hi/lo)
    row_max0<<<SEQ, 256>>>(sp, m0p);
    fetch_kernel<<<SEQ, 256>>>(sp, m0p, fp);
    mask_softmax<<<dim3(SEQ, NHEADS), 256>>>(sp, fp, ph, pl);

    // attn[h] = probs_h @ v_{h/4}  (kcap: probs zero past diagonal; split output fused)
    gemm_mma<<<dim3(1, 8, NHEADS), 256, GEMM_SMEM>>>(ph, pl, vTh, vTl, nullptr, ah, al,
        SEQ, SEQ, SEQ, DMODEL, /*sA=*/(long)SEQ * SEQ, /*sB=*/(long)HDIM * SEQ, /*sC=*/HDIM, 4,
        1.0f, 0, /*kcap=*/1);

    // output projection
    gemm_mma<<<dim3(32, 8, 1), 256, GEMM_SMEM>>>(ah, al, Woh, Wol, out, nullptr, nullptr,
        DMODEL, DMODEL, DMODEL, DMODEL, 0, 0, 0, 1, 1.0f, 0, 0);
}